// round 14
// baseline (speedup 1.0000x reference)
#include <cuda_runtime.h>
#include <cuda_fp16.h>
#include <math.h>
#include <stdint.h>

#define LSEQ 2048
#define DMODEL 2048
#define NH 32
#define NKV 8
#define HD 64
#define NB 2
#define WWIN 1024
#define KVD (NKV*HD)     // 512
#define MROWS (NB*LSEQ)  // 4096
#define PADH 72
#define QKP 72

// ---------------- scratch (fp16) ----------------
static __device__ __half g_xt[(long long)MROWS * DMODEL];
static __device__ __half g_q[(long long)MROWS * DMODEL];
static __device__ __half g_k[(long long)MROWS * KVD];
static __device__ __half g_v[(long long)MROWS * KVD];
static __device__ __half g_ao[(long long)MROWS * DMODEL];
static __device__ __half g_wqt[(long long)DMODEL * DMODEL];
static __device__ __half g_wkt[(long long)KVD * DMODEL];
static __device__ __half g_wvt[(long long)KVD * DMODEL];
static __device__ __half g_wot[(long long)DMODEL * DMODEL];

__host__ __device__ __forceinline__ bool tile_dead(int i0, int j0) {
    return (j0 + 127 < i0) && (j0 >= i0 + 127 - WWIN);
}
__device__ __forceinline__ uint32_t f2h2(float lo, float hi) {
    uint32_t u;
    asm("cvt.rn.f16x2.f32 %0, %1, %2;" : "=r"(u) : "f"(hi), "f"(lo));
    return u;
}
__device__ __forceinline__ void mma16(float* c, const uint32_t* a, const uint32_t* b) {
    asm volatile("mma.sync.aligned.m16n8k16.row.col.f32.f16.f16.f32 "
        "{%0,%1,%2,%3}, {%4,%5,%6,%7}, {%8,%9}, {%0,%1,%2,%3};"
        : "+f"(c[0]), "+f"(c[1]), "+f"(c[2]), "+f"(c[3])
        : "r"(a[0]), "r"(a[1]), "r"(a[2]), "r"(a[3]), "r"(b[0]), "r"(b[1]));
}
__device__ __forceinline__ void ldsm4(uint32_t* r, uint32_t addr) {
    asm volatile("ldmatrix.sync.aligned.m8n8.x4.shared.b16 {%0,%1,%2,%3}, [%4];"
        : "=r"(r[0]), "=r"(r[1]), "=r"(r[2]), "=r"(r[3]) : "r"(addr));
}
__device__ __forceinline__ void ldsm4t(uint32_t* r, uint32_t addr) {
    asm volatile("ldmatrix.sync.aligned.m8n8.x4.trans.shared.b16 {%0,%1,%2,%3}, [%4];"
        : "=r"(r[0]), "=r"(r[1]), "=r"(r[2]), "=r"(r[3]) : "r"(addr));
}

// ---- fp16 GEMM core: 128x128 tile, K-chunk 64, double-buffered, ldmatrix ----
#define GBUFH (128 * PADH * 2)
__device__ __forceinline__ void gemm_core(const __half* __restrict__ A,
                                          const __half* __restrict__ Bt,
                                          long long m0, long long n0, int K,
                                          __half* gsm, int t,
                                          float acc[4][4][4]) {
    const int lane = t & 31;
    const int w = t >> 5, wm = w >> 2, wn = w & 3;
    const int lr = t >> 1, lch = (t & 1) * 32;
    const __half* ap = A + (m0 + lr) * (long long)K + lch;
    const __half* bp = Bt + (n0 + lr) * (long long)K + lch;
    const uint32_t smb = (uint32_t)__cvta_generic_to_shared(gsm);
    const uint32_t a_lane = smb + (((wm * 64 + (lane & 15)) * PADH) + (lane >> 4) * 8) * 2;
    const uint32_t b_lane = smb + ((9216 + (wn * 32 + ((lane >> 4) << 3) + (lane & 7)) * PADH)
                                   + ((lane >> 3) & 1) * 8) * 2;

    uint4 pa[4], pb[4];
    #pragma unroll
    for (int f = 0; f < 4; f++) { pa[f] = *(const uint4*)(ap + f * 8); pb[f] = *(const uint4*)(bp + f * 8); }
    {
        __half* As = gsm; __half* Bs = gsm + 9216;
        #pragma unroll
        for (int f = 0; f < 4; f++) {
            *(uint4*)&As[lr * PADH + lch + f * 8] = pa[f];
            *(uint4*)&Bs[lr * PADH + lch + f * 8] = pb[f];
        }
    }
    __syncthreads();

    const int nch = K / 64;
    for (int c = 0; c < nch; c++) {
        const uint32_t boff = (uint32_t)(c & 1) * GBUFH * 2;
        if (c + 1 < nch) {
            #pragma unroll
            for (int f = 0; f < 4; f++) {
                pa[f] = *(const uint4*)(ap + (c + 1) * 64 + f * 8);
                pb[f] = *(const uint4*)(bp + (c + 1) * 64 + f * 8);
            }
        }
        #pragma unroll
        for (int kk = 0; kk < 4; kk++) {
            const uint32_t koff = kk * 16 * 2;
            uint32_t af[4][4], bf[4][2];
            #pragma unroll
            for (int fm = 0; fm < 4; fm++)
                ldsm4(af[fm], a_lane + boff + fm * (16 * PADH * 2) + koff);
            #pragma unroll
            for (int p = 0; p < 2; p++)
                ldsm4(&bf[p * 2][0], b_lane + boff + p * (16 * PADH * 2) + koff);
            #pragma unroll
            for (int fm = 0; fm < 4; fm++)
                #pragma unroll
                for (int fn = 0; fn < 4; fn++)
                    mma16(acc[fm][fn], af[fm], bf[fn]);
        }
        if (c + 1 < nch) {
            __half* An = gsm + ((c + 1) & 1) * GBUFH;
            __half* Bn = An + 9216;
            #pragma unroll
            for (int f = 0; f < 4; f++) {
                *(uint4*)&An[lr * PADH + lch + f * 8] = pa[f];
                *(uint4*)&Bn[lr * PADH + lch + f * 8] = pb[f];
            }
        }
        __syncthreads();
    }
}

__global__ __launch_bounds__(256, 2) void qkv_gemm(const __half* __restrict__ X,
                                                   const __half* __restrict__ Wq,
                                                   const __half* __restrict__ Wk,
                                                   const __half* __restrict__ Wv,
                                                   __half* __restrict__ Qo,
                                                   __half* __restrict__ Ko,
                                                   __half* __restrict__ Vo) {
    extern __shared__ __half gsm[];
    const int nt = blockIdx.x;
    const __half* Bt; __half* C; long long n0; int N;
    if (nt < 16)      { Bt = Wq; C = Qo; n0 = (long long)nt * 128;        N = DMODEL; }
    else if (nt < 20) { Bt = Wk; C = Ko; n0 = (long long)(nt - 16) * 128; N = KVD; }
    else              { Bt = Wv; C = Vo; n0 = (long long)(nt - 20) * 128; N = KVD; }
    const long long m0 = (long long)blockIdx.y * 128;
    const int t = threadIdx.x, w = t >> 5, lane = t & 31, g = lane >> 2, tg = lane & 3;
    const int wm = w >> 2, wn = w & 3;
    float acc[4][4][4] = {};
    gemm_core(X, Bt, m0, n0, DMODEL, gsm, t, acc);
    #pragma unroll
    for (int fm = 0; fm < 4; fm++) {
        const long long r0 = m0 + wm * 64 + fm * 16 + g;
        #pragma unroll
        for (int fn = 0; fn < 4; fn++) {
            const long long cc = n0 + wn * 32 + fn * 8 + 2 * tg;
            *(uint32_t*)(C + r0 * N + cc)       = f2h2(acc[fm][fn][0], acc[fm][fn][1]);
            *(uint32_t*)(C + (r0 + 8) * N + cc) = f2h2(acc[fm][fn][2], acc[fm][fn][3]);
        }
    }
}

__global__ __launch_bounds__(256, 2) void out_gemm(const __half* __restrict__ A,
                                                   const __half* __restrict__ Bt,
                                                   float* __restrict__ C) {
    extern __shared__ __half gsm[];
    const long long m0 = (long long)blockIdx.y * 128, n0 = (long long)blockIdx.x * 128;
    const int t = threadIdx.x, w = t >> 5, lane = t & 31, g = lane >> 2, tg = lane & 3;
    const int wm = w >> 2, wn = w & 3;
    float acc[4][4][4] = {};
    gemm_core(A, Bt, m0, n0, DMODEL, gsm, t, acc);
    #pragma unroll
    for (int fm = 0; fm < 4; fm++) {
        const long long r0 = m0 + wm * 64 + fm * 16 + g;
        #pragma unroll
        for (int fn = 0; fn < 4; fn++) {
            const long long cc = n0 + wn * 32 + fn * 8 + 2 * tg;
            *(float2*)(C + r0 * DMODEL + cc)       = make_float2(acc[fm][fn][0], acc[fm][fn][1]);
            *(float2*)(C + (r0 + 8) * DMODEL + cc) = make_float2(acc[fm][fn][2], acc[fm][fn][3]);
        }
    }
}

// -------- fused attention: fixed-base softmax + double-buffered KV + trans-V --------
#define A_KV 9216
#define KVBUF 18432
#define ATT_SMB ((9216 + 2 * KVBUF) * 2)   // 92160 B

__global__ __launch_bounds__(256) void attn_fused(const __half* __restrict__ Q,
                                                  const __half* __restrict__ Kg,
                                                  const __half* __restrict__ Vg,
                                                  __half* __restrict__ O) {
    extern __shared__ __half smh[];
    __half* QS = smh;

    const int bh = blockIdx.y, b = bh >> 5, h = bh & 31, kh = h >> 2;
    const int i0 = blockIdx.x * 128;
    const int t = threadIdx.x, w = t >> 5, lane = t & 31, g = lane >> 2, tg = lane & 3;
    const int lr = t >> 1, half = t & 1;
    const uint32_t smb = (uint32_t)__cvta_generic_to_shared(smh);
    const uint32_t k_rel = ((((lane >> 4) << 3) + (lane & 7)) * QKP + ((lane >> 3) & 1) * 8) * 2;
    const uint32_t v_rel = ((lane & 15) * QKP + (lane >> 4) * 8) * 2;

    {   // stage Q tile (128 x 64 halves)
        const __half* qp = Q + ((long long)(b * LSEQ + i0 + lr)) * DMODEL + h * HD + half * 32;
        #pragma unroll
        for (int f = 0; f < 4; f++)
            *(uint4*)&QS[lr * QKP + half * 32 + f * 8] = *(const uint4*)(qp + f * 8);
    }
    const __half* kbase = Kg + ((long long)(b * LSEQ + lr)) * KVD + kh * HD + half * 32;
    const __half* vbase = Vg + ((long long)(b * LSEQ + lr)) * KVD + kh * HD + half * 32;

    int aj[16], na = 0;
    #pragma unroll
    for (int jt = 0; jt < 16; jt++) {
        const int j0 = jt << 7;
        if (!tile_dead(i0, j0)) aj[na++] = j0;
    }

    uint4 kpre[4], vpre[4];
    {
        const __half* kp = kbase + (long long)aj[0] * KVD;
        const __half* vp = vbase + (long long)aj[0] * KVD;
        #pragma unroll
        for (int f = 0; f < 4; f++) { kpre[f] = *(const uint4*)(kp + f * 8); vpre[f] = *(const uint4*)(vp + f * 8); }
        __half* KS0 = smh + A_KV;
        __half* VS0 = KS0 + 9216;
        #pragma unroll
        for (int f = 0; f < 4; f++) {
            *(uint4*)&KS0[lr * QKP + half * 32 + f * 8] = kpre[f];
            *(uint4*)&VS0[lr * QKP + half * 32 + f * 8] = vpre[f];
        }
    }
    __syncthreads();

    uint32_t qf[4][4];
    const int rw = w * 16 + g;
    {
        const uint32_t q_lane = smb + (((w * 16 + (lane & 15)) * QKP) + (lane >> 4) * 8) * 2;
        #pragma unroll
        for (int kk = 0; kk < 4; kk++)
            ldsm4(qf[kk], q_lane + kk * 16 * 2);
    }

    const int gi0 = i0 + rw, gi1 = gi0 + 8;
    float l0 = 0.0f, l1 = 0.0f;
    float oacc[8][4] = {};

    for (int ci = 0; ci < na; ci++) {
        const int j0 = aj[ci];
        const uint32_t kvo = (uint32_t)(ci & 1) * KVBUF * 2;
        const uint32_t k_lane = smb + (A_KV * 2) + kvo + k_rel;
        const uint32_t v_lane = smb + ((A_KV + 9216) * 2) + kvo + v_rel;

        if (ci + 1 < na) {
            const int jn = aj[ci + 1];
            const __half* kp = kbase + (long long)jn * KVD;
            const __half* vp = vbase + (long long)jn * KVD;
            #pragma unroll
            for (int f = 0; f < 4; f++) { kpre[f] = *(const uint4*)(kp + f * 8); vpre[f] = *(const uint4*)(vp + f * 8); }
        }

        float sacc[16][4] = {};
        #pragma unroll
        for (int kk = 0; kk < 4; kk++) {
            const uint32_t koff = kk * 16 * 2;
            #pragma unroll
            for (int p = 0; p < 8; p++) {
                uint32_t bf[4];
                ldsm4(bf, k_lane + p * (16 * QKP * 2) + koff);
                mma16(sacc[2 * p],     qf[kk], bf);
                mma16(sacc[2 * p + 1], qf[kk], bf + 2);
            }
        }

        if (ci + 1 < na) {
            __half* KSn = smh + A_KV + ((ci + 1) & 1) * KVBUF;
            __half* VSn = KSn + 9216;
            #pragma unroll
            for (int f = 0; f < 4; f++) {
                *(uint4*)&KSn[lr * QKP + half * 32 + f * 8] = kpre[f];
                *(uint4*)&VSn[lr * QKP + half * 32 + f * 8] = vpre[f];
            }
        }

        uint32_t ph0[16], ph1[16];
        float rs0 = 0.0f, rs1 = 0.0f;
        #pragma unroll
        for (int fn = 0; fn < 16; fn++) {
            float p0[2], p1[2];
            #pragma unroll
            for (int e = 0; e < 2; e++) {
                const int gj = j0 + fn * 8 + 2 * tg + e;
                const bool m0 = (gj >= gi0 - WWIN) && (gj < gi0);
                const bool m1 = (gj >= gi1 - WWIN) && (gj < gi1);
                p0[e] = m0 ? 0.0f : __expf(sacc[fn][e] * 0.125f);
                p1[e] = m1 ? 0.0f : __expf(sacc[fn][2 + e] * 0.125f);
            }
            rs0 += p0[0] + p0[1]; rs1 += p1[0] + p1[1];
            ph0[fn] = f2h2(p0[0], p0[1]);
            ph1[fn] = f2h2(p1[0], p1[1]);
        }
        rs0 += __shfl_xor_sync(0xffffffffu, rs0, 1);
        rs0 += __shfl_xor_sync(0xffffffffu, rs0, 2);
        rs1 += __shfl_xor_sync(0xffffffffu, rs1, 1);
        rs1 += __shfl_xor_sync(0xffffffffu, rs1, 2);
        l0 += rs0; l1 += rs1;

        #pragma unroll
        for (int kk = 0; kk < 8; kk++) {
            const uint32_t jo = kk * (16 * QKP * 2);
            uint32_t af[4] = { ph0[2 * kk], ph1[2 * kk], ph0[2 * kk + 1], ph1[2 * kk + 1] };
            #pragma unroll
            for (int p = 0; p < 4; p++) {
                uint32_t bf[4];
                ldsm4t(bf, v_lane + jo + p * 16 * 2);
                mma16(oacc[2 * p],     af, bf);
                mma16(oacc[2 * p + 1], af, bf + 2);
            }
        }
        __syncthreads();
    }

    const float inv0 = 1.0f / l0, inv1 = 1.0f / l1;
    __half* orow = O + ((long long)(b * LSEQ) + i0 + rw) * DMODEL + h * HD;
    #pragma unroll
    for (int fd = 0; fd < 8; fd++) {
        const int cc = fd * 8 + 2 * tg;
        *(uint32_t*)(orow + cc) = f2h2(oacc[fd][0] * inv0, oacc[fd][1] * inv0);
        *(uint32_t*)(orow + 8LL * DMODEL + cc) = f2h2(oacc[fd][2] * inv1, oacc[fd][3] * inv1);
    }
}

// -------- merged prep: cvt_x + 4 weight transposes in one launch --------
// blocks 0..4095: cvt_x (2048 f32 each)
// then transposes (32x32 tiles, 256 threads): wq 4096, wk 1024, wv 1024, wo 4096
__device__ __forceinline__ void do_transpose(const float* __restrict__ src,
                                             __half* __restrict__ dst,
                                             int R, int C, int tile, int t) {
    __shared__ __half tb[32][33];
    const int tilesx = C / 32;
    const int c = (tile % tilesx) * 32, r = (tile / tilesx) * 32;
    const int tx = t & 31, ty = t >> 5;
    #pragma unroll
    for (int i = 0; i < 32; i += 8) tb[ty + i][tx] = __float2half_rn(src[(long long)(r + ty + i) * C + c + tx]);
    __syncthreads();
    #pragma unroll
    for (int i = 0; i < 32; i += 8) dst[(long long)(c + ty + i) * R + r + tx] = tb[tx][ty + i];
}
__global__ void prep_kernel(const float* __restrict__ x,
                            const float* __restrict__ wq,
                            const float* __restrict__ wk,
                            const float* __restrict__ wv,
                            const float* __restrict__ wo,
                            __half* __restrict__ xt,
                            __half* __restrict__ wqt,
                            __half* __restrict__ wkt,
                            __half* __restrict__ wvt,
                            __half* __restrict__ wot) {
    const int blk = blockIdx.x, t = threadIdx.x;
    if (blk < 4096) {
        const long long i = ((long long)blk * 256 + t) * 8;
        float4 v0 = *(const float4*)(x + i);
        float4 v1 = *(const float4*)(x + i + 4);
        uint4 u;
        u.x = f2h2(v0.x, v0.y); u.y = f2h2(v0.z, v0.w);
        u.z = f2h2(v1.x, v1.y); u.w = f2h2(v1.z, v1.w);
        *(uint4*)(xt + i) = u;
    } else if (blk < 8192) {
        do_transpose(wq, wqt, DMODEL, DMODEL, blk - 4096, t);
    } else if (blk < 9216) {
        do_transpose(wk, wkt, DMODEL, KVD, blk - 8192, t);
    } else if (blk < 10240) {
        do_transpose(wv, wvt, DMODEL, KVD, blk - 9216, t);
    } else {
        do_transpose(wo, wot, DMODEL, DMODEL, blk - 10240, t);
    }
}

// ---------------- launch ----------------
extern "C" void kernel_launch(void* const* d_in, const int* in_sizes, int n_in,
                              void* d_out, int out_size) {
    const float* x  = (const float*)d_in[0];
    const float* wq = (const float*)d_in[1];
    const float* wk = (const float*)d_in[2];
    const float* wv = (const float*)d_in[3];
    const float* wo = (const float*)d_in[4];
    float* out = (float*)d_out;

    __half *xt, *qb, *kb, *vb, *ab, *wqt, *wkt, *wvt, *wot;
    cudaGetSymbolAddress((void**)&xt, g_xt);
    cudaGetSymbolAddress((void**)&qb, g_q);
    cudaGetSymbolAddress((void**)&kb, g_k);
    cudaGetSymbolAddress((void**)&vb, g_v);
    cudaGetSymbolAddress((void**)&ab, g_ao);
    cudaGetSymbolAddress((void**)&wqt, g_wqt);
    cudaGetSymbolAddress((void**)&wkt, g_wkt);
    cudaGetSymbolAddress((void**)&wvt, g_wvt);
    cudaGetSymbolAddress((void**)&wot, g_wot);

    const int GEMM_SM = 2 * GBUFH * 2;      // 73728 B
    cudaFuncSetAttribute(qkv_gemm,   cudaFuncAttributeMaxDynamicSharedMemorySize, GEMM_SM);
    cudaFuncSetAttribute(out_gemm,   cudaFuncAttributeMaxDynamicSharedMemorySize, GEMM_SM);
    cudaFuncSetAttribute(attn_fused, cudaFuncAttributeMaxDynamicSharedMemorySize, ATT_SMB);

    prep_kernel<<<dim3(14336), 256>>>(x, wq, wk, wv, wo, xt, wqt, wkt, wvt, wot);

    qkv_gemm<<<dim3(24, 32), 256, GEMM_SM>>>(xt, wqt, wkt, wvt, qb, kb, vb);

    attn_fused<<<dim3(16, 64), 256, ATT_SMB>>>(qb, kb, vb, ab);

    out_gemm<<<dim3(16, 32), 256, GEMM_SM>>>(ab, wot, out);
}

// round 15
// speedup vs baseline: 1.0527x; 1.0527x over previous
#include <cuda_runtime.h>
#include <cuda_fp16.h>
#include <math.h>
#include <stdint.h>

#define LSEQ 2048
#define DMODEL 2048
#define NH 32
#define NKV 8
#define HD 64
#define NB 2
#define WWIN 1024
#define KVD (NKV*HD)     // 512
#define MROWS (NB*LSEQ)  // 4096
#define PADH 72
#define QKP 72

// ---------------- scratch (fp16) ----------------
static __device__ __half g_xt[(long long)MROWS * DMODEL];
static __device__ __half g_q[(long long)MROWS * DMODEL];
static __device__ __half g_k[(long long)MROWS * KVD];
static __device__ __half g_v[(long long)MROWS * KVD];
static __device__ __half g_ao[(long long)MROWS * DMODEL];
static __device__ __half g_wqt[(long long)DMODEL * DMODEL];
static __device__ __half g_wkt[(long long)KVD * DMODEL];
static __device__ __half g_wvt[(long long)KVD * DMODEL];
static __device__ __half g_wot[(long long)DMODEL * DMODEL];

__host__ __device__ __forceinline__ bool tile_dead(int i0, int j0) {
    return (j0 + 127 < i0) && (j0 >= i0 + 127 - WWIN);
}
__device__ __forceinline__ uint32_t f2h2(float lo, float hi) {
    uint32_t u;
    asm("cvt.rn.f16x2.f32 %0, %1, %2;" : "=r"(u) : "f"(hi), "f"(lo));
    return u;
}
__device__ __forceinline__ void mma16(float* c, const uint32_t* a, const uint32_t* b) {
    asm volatile("mma.sync.aligned.m16n8k16.row.col.f32.f16.f16.f32 "
        "{%0,%1,%2,%3}, {%4,%5,%6,%7}, {%8,%9}, {%0,%1,%2,%3};"
        : "+f"(c[0]), "+f"(c[1]), "+f"(c[2]), "+f"(c[3])
        : "r"(a[0]), "r"(a[1]), "r"(a[2]), "r"(a[3]), "r"(b[0]), "r"(b[1]));
}
__device__ __forceinline__ void ldsm4(uint32_t* r, uint32_t addr) {
    asm volatile("ldmatrix.sync.aligned.m8n8.x4.shared.b16 {%0,%1,%2,%3}, [%4];"
        : "=r"(r[0]), "=r"(r[1]), "=r"(r[2]), "=r"(r[3]) : "r"(addr));
}
__device__ __forceinline__ void ldsm4t(uint32_t* r, uint32_t addr) {
    asm volatile("ldmatrix.sync.aligned.m8n8.x4.trans.shared.b16 {%0,%1,%2,%3}, [%4];"
        : "=r"(r[0]), "=r"(r[1]), "=r"(r[2]), "=r"(r[3]) : "r"(addr));
}

// ---- fp16 GEMM core: 128x128 tile, K-chunk 64, double-buffered, ldmatrix ----
#define GBUFH (128 * PADH * 2)
__device__ __forceinline__ void gemm_core(const __half* __restrict__ A,
                                          const __half* __restrict__ Bt,
                                          long long m0, long long n0, int K,
                                          __half* gsm, int t,
                                          float acc[4][4][4]) {
    const int lane = t & 31;
    const int w = t >> 5, wm = w >> 2, wn = w & 3;
    const int lr = t >> 1, lch = (t & 1) * 32;
    const __half* ap = A + (m0 + lr) * (long long)K + lch;
    const __half* bp = Bt + (n0 + lr) * (long long)K + lch;
    const uint32_t smb = (uint32_t)__cvta_generic_to_shared(gsm);
    const uint32_t a_lane = smb + (((wm * 64 + (lane & 15)) * PADH) + (lane >> 4) * 8) * 2;
    const uint32_t b_lane = smb + ((9216 + (wn * 32 + ((lane >> 4) << 3) + (lane & 7)) * PADH)
                                   + ((lane >> 3) & 1) * 8) * 2;

    uint4 pa[4], pb[4];
    #pragma unroll
    for (int f = 0; f < 4; f++) { pa[f] = *(const uint4*)(ap + f * 8); pb[f] = *(const uint4*)(bp + f * 8); }
    {
        __half* As = gsm; __half* Bs = gsm + 9216;
        #pragma unroll
        for (int f = 0; f < 4; f++) {
            *(uint4*)&As[lr * PADH + lch + f * 8] = pa[f];
            *(uint4*)&Bs[lr * PADH + lch + f * 8] = pb[f];
        }
    }
    __syncthreads();

    const int nch = K / 64;
    for (int c = 0; c < nch; c++) {
        const uint32_t boff = (uint32_t)(c & 1) * GBUFH * 2;
        if (c + 1 < nch) {
            #pragma unroll
            for (int f = 0; f < 4; f++) {
                pa[f] = *(const uint4*)(ap + (c + 1) * 64 + f * 8);
                pb[f] = *(const uint4*)(bp + (c + 1) * 64 + f * 8);
            }
        }
        #pragma unroll
        for (int kk = 0; kk < 4; kk++) {
            const uint32_t koff = kk * 16 * 2;
            uint32_t af[4][4], bf[4][2];
            #pragma unroll
            for (int fm = 0; fm < 4; fm++)
                ldsm4(af[fm], a_lane + boff + fm * (16 * PADH * 2) + koff);
            #pragma unroll
            for (int p = 0; p < 2; p++)
                ldsm4(&bf[p * 2][0], b_lane + boff + p * (16 * PADH * 2) + koff);
            #pragma unroll
            for (int fm = 0; fm < 4; fm++)
                #pragma unroll
                for (int fn = 0; fn < 4; fn++)
                    mma16(acc[fm][fn], af[fm], bf[fn]);
        }
        if (c + 1 < nch) {
            __half* An = gsm + ((c + 1) & 1) * GBUFH;
            __half* Bn = An + 9216;
            #pragma unroll
            for (int f = 0; f < 4; f++) {
                *(uint4*)&An[lr * PADH + lch + f * 8] = pa[f];
                *(uint4*)&Bn[lr * PADH + lch + f * 8] = pb[f];
            }
        }
        __syncthreads();
    }
}

__global__ __launch_bounds__(256) void qkv_gemm(const __half* __restrict__ X,
                                                const __half* __restrict__ Wq,
                                                const __half* __restrict__ Wk,
                                                const __half* __restrict__ Wv,
                                                __half* __restrict__ Qo,
                                                __half* __restrict__ Ko,
                                                __half* __restrict__ Vo) {
    extern __shared__ __half gsm[];
    const int nt = blockIdx.x;
    const __half* Bt; __half* C; long long n0; int N;
    if (nt < 16)      { Bt = Wq; C = Qo; n0 = (long long)nt * 128;        N = DMODEL; }
    else if (nt < 20) { Bt = Wk; C = Ko; n0 = (long long)(nt - 16) * 128; N = KVD; }
    else              { Bt = Wv; C = Vo; n0 = (long long)(nt - 20) * 128; N = KVD; }
    const long long m0 = (long long)blockIdx.y * 128;
    const int t = threadIdx.x, w = t >> 5, lane = t & 31, g = lane >> 2, tg = lane & 3;
    const int wm = w >> 2, wn = w & 3;
    float acc[4][4][4] = {};
    gemm_core(X, Bt, m0, n0, DMODEL, gsm, t, acc);
    #pragma unroll
    for (int fm = 0; fm < 4; fm++) {
        const long long r0 = m0 + wm * 64 + fm * 16 + g;
        #pragma unroll
        for (int fn = 0; fn < 4; fn++) {
            const long long cc = n0 + wn * 32 + fn * 8 + 2 * tg;
            *(uint32_t*)(C + r0 * N + cc)       = f2h2(acc[fm][fn][0], acc[fm][fn][1]);
            *(uint32_t*)(C + (r0 + 8) * N + cc) = f2h2(acc[fm][fn][2], acc[fm][fn][3]);
        }
    }
}

__global__ __launch_bounds__(256) void out_gemm(const __half* __restrict__ A,
                                                const __half* __restrict__ Bt,
                                                float* __restrict__ C) {
    extern __shared__ __half gsm[];
    const long long m0 = (long long)blockIdx.y * 128, n0 = (long long)blockIdx.x * 128;
    const int t = threadIdx.x, w = t >> 5, lane = t & 31, g = lane >> 2, tg = lane & 3;
    const int wm = w >> 2, wn = w & 3;
    float acc[4][4][4] = {};
    gemm_core(A, Bt, m0, n0, DMODEL, gsm, t, acc);
    #pragma unroll
    for (int fm = 0; fm < 4; fm++) {
        const long long r0 = m0 + wm * 64 + fm * 16 + g;
        #pragma unroll
        for (int fn = 0; fn < 4; fn++) {
            const long long cc = n0 + wn * 32 + fn * 8 + 2 * tg;
            *(float2*)(C + r0 * DMODEL + cc)       = make_float2(acc[fm][fn][0], acc[fm][fn][1]);
            *(float2*)(C + (r0 + 8) * DMODEL + cc) = make_float2(acc[fm][fn][2], acc[fm][fn][3]);
        }
    }
}

// -------- fused attention: fixed-base softmax + double-buffered KV + trans-V --------
#define A_KV 9216
#define KVBUF 18432
#define ATT_SMB ((9216 + 2 * KVBUF) * 2)   // 92160 B

__global__ __launch_bounds__(256) void attn_fused(const __half* __restrict__ Q,
                                                  const __half* __restrict__ Kg,
                                                  const __half* __restrict__ Vg,
                                                  __half* __restrict__ O) {
    extern __shared__ __half smh[];
    __half* QS = smh;

    const int bh = blockIdx.y, b = bh >> 5, h = bh & 31, kh = h >> 2;
    const int i0 = blockIdx.x * 128;
    const int t = threadIdx.x, w = t >> 5, lane = t & 31, g = lane >> 2, tg = lane & 3;
    const int lr = t >> 1, half = t & 1;
    const uint32_t smb = (uint32_t)__cvta_generic_to_shared(smh);
    const uint32_t k_rel = ((((lane >> 4) << 3) + (lane & 7)) * QKP + ((lane >> 3) & 1) * 8) * 2;
    const uint32_t v_rel = ((lane & 15) * QKP + (lane >> 4) * 8) * 2;

    {   // stage Q tile (128 x 64 halves)
        const __half* qp = Q + ((long long)(b * LSEQ + i0 + lr)) * DMODEL + h * HD + half * 32;
        #pragma unroll
        for (int f = 0; f < 4; f++)
            *(uint4*)&QS[lr * QKP + half * 32 + f * 8] = *(const uint4*)(qp + f * 8);
    }
    const __half* kbase = Kg + ((long long)(b * LSEQ + lr)) * KVD + kh * HD + half * 32;
    const __half* vbase = Vg + ((long long)(b * LSEQ + lr)) * KVD + kh * HD + half * 32;

    int aj[16], na = 0;
    #pragma unroll
    for (int jt = 0; jt < 16; jt++) {
        const int j0 = jt << 7;
        if (!tile_dead(i0, j0)) aj[na++] = j0;
    }

    uint4 kpre[4], vpre[4];
    {
        const __half* kp = kbase + (long long)aj[0] * KVD;
        const __half* vp = vbase + (long long)aj[0] * KVD;
        #pragma unroll
        for (int f = 0; f < 4; f++) { kpre[f] = *(const uint4*)(kp + f * 8); vpre[f] = *(const uint4*)(vp + f * 8); }
        __half* KS0 = smh + A_KV;
        __half* VS0 = KS0 + 9216;
        #pragma unroll
        for (int f = 0; f < 4; f++) {
            *(uint4*)&KS0[lr * QKP + half * 32 + f * 8] = kpre[f];
            *(uint4*)&VS0[lr * QKP + half * 32 + f * 8] = vpre[f];
        }
    }
    __syncthreads();

    uint32_t qf[4][4];
    const int rw = w * 16 + g;
    {
        const uint32_t q_lane = smb + (((w * 16 + (lane & 15)) * QKP) + (lane >> 4) * 8) * 2;
        #pragma unroll
        for (int kk = 0; kk < 4; kk++)
            ldsm4(qf[kk], q_lane + kk * 16 * 2);
    }

    const int gi0 = i0 + rw, gi1 = gi0 + 8;
    float l0 = 0.0f, l1 = 0.0f;
    float oacc[8][4] = {};

    for (int ci = 0; ci < na; ci++) {
        const int j0 = aj[ci];
        const uint32_t kvo = (uint32_t)(ci & 1) * KVBUF * 2;
        const uint32_t k_lane = smb + (A_KV * 2) + kvo + k_rel;
        const uint32_t v_lane = smb + ((A_KV + 9216) * 2) + kvo + v_rel;

        if (ci + 1 < na) {
            const int jn = aj[ci + 1];
            const __half* kp = kbase + (long long)jn * KVD;
            const __half* vp = vbase + (long long)jn * KVD;
            #pragma unroll
            for (int f = 0; f < 4; f++) { kpre[f] = *(const uint4*)(kp + f * 8); vpre[f] = *(const uint4*)(vp + f * 8); }
        }

        float sacc[16][4] = {};
        #pragma unroll
        for (int kk = 0; kk < 4; kk++) {
            const uint32_t koff = kk * 16 * 2;
            #pragma unroll
            for (int p = 0; p < 8; p++) {
                uint32_t bf[4];
                ldsm4(bf, k_lane + p * (16 * QKP * 2) + koff);
                mma16(sacc[2 * p],     qf[kk], bf);
                mma16(sacc[2 * p + 1], qf[kk], bf + 2);
            }
        }

        if (ci + 1 < na) {
            __half* KSn = smh + A_KV + ((ci + 1) & 1) * KVBUF;
            __half* VSn = KSn + 9216;
            #pragma unroll
            for (int f = 0; f < 4; f++) {
                *(uint4*)&KSn[lr * QKP + half * 32 + f * 8] = kpre[f];
                *(uint4*)&VSn[lr * QKP + half * 32 + f * 8] = vpre[f];
            }
        }

        uint32_t ph0[16], ph1[16];
        float rs0 = 0.0f, rs1 = 0.0f;
        #pragma unroll
        for (int fn = 0; fn < 16; fn++) {
            float p0[2], p1[2];
            #pragma unroll
            for (int e = 0; e < 2; e++) {
                const int gj = j0 + fn * 8 + 2 * tg + e;
                const bool m0 = (gj >= gi0 - WWIN) && (gj < gi0);
                const bool m1 = (gj >= gi1 - WWIN) && (gj < gi1);
                p0[e] = m0 ? 0.0f : __expf(sacc[fn][e] * 0.125f);
                p1[e] = m1 ? 0.0f : __expf(sacc[fn][2 + e] * 0.125f);
            }
            rs0 += p0[0] + p0[1]; rs1 += p1[0] + p1[1];
            ph0[fn] = f2h2(p0[0], p0[1]);
            ph1[fn] = f2h2(p1[0], p1[1]);
        }
        rs0 += __shfl_xor_sync(0xffffffffu, rs0, 1);
        rs0 += __shfl_xor_sync(0xffffffffu, rs0, 2);
        rs1 += __shfl_xor_sync(0xffffffffu, rs1, 1);
        rs1 += __shfl_xor_sync(0xffffffffu, rs1, 2);
        l0 += rs0; l1 += rs1;

        #pragma unroll
        for (int kk = 0; kk < 8; kk++) {
            const uint32_t jo = kk * (16 * QKP * 2);
            uint32_t af[4] = { ph0[2 * kk], ph1[2 * kk], ph0[2 * kk + 1], ph1[2 * kk + 1] };
            #pragma unroll
            for (int p = 0; p < 4; p++) {
                uint32_t bf[4];
                ldsm4t(bf, v_lane + jo + p * 16 * 2);
                mma16(oacc[2 * p],     af, bf);
                mma16(oacc[2 * p + 1], af, bf + 2);
            }
        }
        __syncthreads();
    }

    const float inv0 = 1.0f / l0, inv1 = 1.0f / l1;
    __half* orow = O + ((long long)(b * LSEQ) + i0 + rw) * DMODEL + h * HD;
    #pragma unroll
    for (int fd = 0; fd < 8; fd++) {
        const int cc = fd * 8 + 2 * tg;
        *(uint32_t*)(orow + cc) = f2h2(oacc[fd][0] * inv0, oacc[fd][1] * inv0);
        *(uint32_t*)(orow + 8LL * DMODEL + cc) = f2h2(oacc[fd][2] * inv1, oacc[fd][3] * inv1);
    }
}

// -------- merged prep: cvt_x + 4 weight transposes in one launch --------
__device__ __forceinline__ void do_transpose(const float* __restrict__ src,
                                             __half* __restrict__ dst,
                                             int R, int C, int tile, int t) {
    __shared__ __half tb[32][33];
    const int tilesx = C / 32;
    const int c = (tile % tilesx) * 32, r = (tile / tilesx) * 32;
    const int tx = t & 31, ty = t >> 5;
    #pragma unroll
    for (int i = 0; i < 32; i += 8) tb[ty + i][tx] = __float2half_rn(src[(long long)(r + ty + i) * C + c + tx]);
    __syncthreads();
    #pragma unroll
    for (int i = 0; i < 32; i += 8) dst[(long long)(c + ty + i) * R + r + tx] = tb[tx][ty + i];
}
__global__ void prep_kernel(const float* __restrict__ x,
                            const float* __restrict__ wq,
                            const float* __restrict__ wk,
                            const float* __restrict__ wv,
                            const float* __restrict__ wo,
                            __half* __restrict__ xt,
                            __half* __restrict__ wqt,
                            __half* __restrict__ wkt,
                            __half* __restrict__ wvt,
                            __half* __restrict__ wot) {
    const int blk = blockIdx.x, t = threadIdx.x;
    if (blk < 4096) {
        const long long i = ((long long)blk * 256 + t) * 8;
        float4 v0 = *(const float4*)(x + i);
        float4 v1 = *(const float4*)(x + i + 4);
        uint4 u;
        u.x = f2h2(v0.x, v0.y); u.y = f2h2(v0.z, v0.w);
        u.z = f2h2(v1.x, v1.y); u.w = f2h2(v1.z, v1.w);
        *(uint4*)(xt + i) = u;
    } else if (blk < 8192) {
        do_transpose(wq, wqt, DMODEL, DMODEL, blk - 4096, t);
    } else if (blk < 9216) {
        do_transpose(wk, wkt, DMODEL, KVD, blk - 8192, t);
    } else if (blk < 10240) {
        do_transpose(wv, wvt, DMODEL, KVD, blk - 9216, t);
    } else {
        do_transpose(wo, wot, DMODEL, DMODEL, blk - 10240, t);
    }
}

// ---------------- launch ----------------
extern "C" void kernel_launch(void* const* d_in, const int* in_sizes, int n_in,
                              void* d_out, int out_size) {
    const float* x  = (const float*)d_in[0];
    const float* wq = (const float*)d_in[1];
    const float* wk = (const float*)d_in[2];
    const float* wv = (const float*)d_in[3];
    const float* wo = (const float*)d_in[4];
    float* out = (float*)d_out;

    __half *xt, *qb, *kb, *vb, *ab, *wqt, *wkt, *wvt, *wot;
    cudaGetSymbolAddress((void**)&xt, g_xt);
    cudaGetSymbolAddress((void**)&qb, g_q);
    cudaGetSymbolAddress((void**)&kb, g_k);
    cudaGetSymbolAddress((void**)&vb, g_v);
    cudaGetSymbolAddress((void**)&ab, g_ao);
    cudaGetSymbolAddress((void**)&wqt, g_wqt);
    cudaGetSymbolAddress((void**)&wkt, g_wkt);
    cudaGetSymbolAddress((void**)&wvt, g_wvt);
    cudaGetSymbolAddress((void**)&wot, g_wot);

    const int GEMM_SM = 2 * GBUFH * 2;      // 73728 B
    cudaFuncSetAttribute(qkv_gemm,   cudaFuncAttributeMaxDynamicSharedMemorySize, GEMM_SM);
    cudaFuncSetAttribute(out_gemm,   cudaFuncAttributeMaxDynamicSharedMemorySize, GEMM_SM);
    cudaFuncSetAttribute(attn_fused, cudaFuncAttributeMaxDynamicSharedMemorySize, ATT_SMB);

    prep_kernel<<<dim3(14336), 256>>>(x, wq, wk, wv, wo, xt, wqt, wkt, wvt, wot);

    qkv_gemm<<<dim3(24, 32), 256, GEMM_SM>>>(xt, wqt, wkt, wvt, qb, kb, vb);

    attn_fused<<<dim3(16, 64), 256, ATT_SMB>>>(qb, kb, vb, ab);

    out_gemm<<<dim3(16, 32), 256, GEMM_SM>>>(ab, wot, out);
}

// round 16
// speedup vs baseline: 1.1023x; 1.0471x over previous
#include <cuda_runtime.h>
#include <cuda_fp16.h>
#include <math.h>
#include <stdint.h>

#define LSEQ 2048
#define DMODEL 2048
#define NH 32
#define NKV 8
#define HD 64
#define NB 2
#define WWIN 1024
#define KVD (NKV*HD)     // 512
#define MROWS (NB*LSEQ)  // 4096
#define PADH 72
#define QKP 72
#define EXSC 0.18033688f   // 0.125 * log2(e)

// ---------------- scratch (fp16) ----------------
static __device__ __half g_xt[(long long)MROWS * DMODEL];
static __device__ __half g_q[(long long)MROWS * DMODEL];
static __device__ __half g_k[(long long)MROWS * KVD];
static __device__ __half g_v[(long long)MROWS * KVD];
static __device__ __half g_ao[(long long)MROWS * DMODEL];
static __device__ __half g_wqt[(long long)DMODEL * DMODEL];
static __device__ __half g_wkt[(long long)KVD * DMODEL];
static __device__ __half g_wvt[(long long)KVD * DMODEL];
static __device__ __half g_wot[(long long)DMODEL * DMODEL];

__host__ __device__ __forceinline__ bool tile_dead(int i0, int j0) {
    return (j0 + 127 < i0) && (j0 >= i0 + 127 - WWIN);
}
__device__ __forceinline__ uint32_t f2h2(float lo, float hi) {
    uint32_t u;
    asm("cvt.rn.f16x2.f32 %0, %1, %2;" : "=r"(u) : "f"(hi), "f"(lo));
    return u;
}
__device__ __forceinline__ void mma16(float* c, const uint32_t* a, const uint32_t* b) {
    asm volatile("mma.sync.aligned.m16n8k16.row.col.f32.f16.f16.f32 "
        "{%0,%1,%2,%3}, {%4,%5,%6,%7}, {%8,%9}, {%0,%1,%2,%3};"
        : "+f"(c[0]), "+f"(c[1]), "+f"(c[2]), "+f"(c[3])
        : "r"(a[0]), "r"(a[1]), "r"(a[2]), "r"(a[3]), "r"(b[0]), "r"(b[1]));
}
__device__ __forceinline__ void ldsm4(uint32_t* r, uint32_t addr) {
    asm volatile("ldmatrix.sync.aligned.m8n8.x4.shared.b16 {%0,%1,%2,%3}, [%4];"
        : "=r"(r[0]), "=r"(r[1]), "=r"(r[2]), "=r"(r[3]) : "r"(addr));
}
__device__ __forceinline__ void ldsm4t(uint32_t* r, uint32_t addr) {
    asm volatile("ldmatrix.sync.aligned.m8n8.x4.trans.shared.b16 {%0,%1,%2,%3}, [%4];"
        : "=r"(r[0]), "=r"(r[1]), "=r"(r[2]), "=r"(r[3]) : "r"(addr));
}

// ---- fp16 GEMM core: 128x128 tile, K-chunk 64, double-buffered, ldmatrix ----
#define GBUFH (128 * PADH * 2)
__device__ __forceinline__ void gemm_core(const __half* __restrict__ A,
                                          const __half* __restrict__ Bt,
                                          long long m0, long long n0, int K,
                                          __half* gsm, int t,
                                          float acc[4][4][4]) {
    const int lane = t & 31;
    const int w = t >> 5, wm = w >> 2, wn = w & 3;
    const int lr = t >> 1, lch = (t & 1) * 32;
    const __half* ap = A + (m0 + lr) * (long long)K + lch;
    const __half* bp = Bt + (n0 + lr) * (long long)K + lch;
    const uint32_t smb = (uint32_t)__cvta_generic_to_shared(gsm);
    const uint32_t a_lane = smb + (((wm * 64 + (lane & 15)) * PADH) + (lane >> 4) * 8) * 2;
    const uint32_t b_lane = smb + ((9216 + (wn * 32 + ((lane >> 4) << 3) + (lane & 7)) * PADH)
                                   + ((lane >> 3) & 1) * 8) * 2;

    uint4 pa[4], pb[4];
    #pragma unroll
    for (int f = 0; f < 4; f++) { pa[f] = *(const uint4*)(ap + f * 8); pb[f] = *(const uint4*)(bp + f * 8); }
    {
        __half* As = gsm; __half* Bs = gsm + 9216;
        #pragma unroll
        for (int f = 0; f < 4; f++) {
            *(uint4*)&As[lr * PADH + lch + f * 8] = pa[f];
            *(uint4*)&Bs[lr * PADH + lch + f * 8] = pb[f];
        }
    }
    __syncthreads();

    const int nch = K / 64;
    for (int c = 0; c < nch; c++) {
        const uint32_t boff = (uint32_t)(c & 1) * GBUFH * 2;
        if (c + 1 < nch) {
            #pragma unroll
            for (int f = 0; f < 4; f++) {
                pa[f] = *(const uint4*)(ap + (c + 1) * 64 + f * 8);
                pb[f] = *(const uint4*)(bp + (c + 1) * 64 + f * 8);
            }
        }
        #pragma unroll
        for (int kk = 0; kk < 4; kk++) {
            const uint32_t koff = kk * 16 * 2;
            uint32_t af[4][4], bf[4][2];
            #pragma unroll
            for (int fm = 0; fm < 4; fm++)
                ldsm4(af[fm], a_lane + boff + fm * (16 * PADH * 2) + koff);
            #pragma unroll
            for (int p = 0; p < 2; p++)
                ldsm4(&bf[p * 2][0], b_lane + boff + p * (16 * PADH * 2) + koff);
            #pragma unroll
            for (int fm = 0; fm < 4; fm++)
                #pragma unroll
                for (int fn = 0; fn < 4; fn++)
                    mma16(acc[fm][fn], af[fm], bf[fn]);
        }
        if (c + 1 < nch) {
            __half* An = gsm + ((c + 1) & 1) * GBUFH;
            __half* Bn = An + 9216;
            #pragma unroll
            for (int f = 0; f < 4; f++) {
                *(uint4*)&An[lr * PADH + lch + f * 8] = pa[f];
                *(uint4*)&Bn[lr * PADH + lch + f * 8] = pb[f];
            }
        }
        __syncthreads();
    }
}

__global__ __launch_bounds__(256) void qkv_gemm(const __half* __restrict__ X,
                                                const __half* __restrict__ Wq,
                                                const __half* __restrict__ Wk,
                                                const __half* __restrict__ Wv,
                                                __half* __restrict__ Qo,
                                                __half* __restrict__ Ko,
                                                __half* __restrict__ Vo) {
    extern __shared__ __half gsm[];
    const int nt = blockIdx.x;
    const __half* Bt; __half* C; long long n0; int N;
    if (nt < 16)      { Bt = Wq; C = Qo; n0 = (long long)nt * 128;        N = DMODEL; }
    else if (nt < 20) { Bt = Wk; C = Ko; n0 = (long long)(nt - 16) * 128; N = KVD; }
    else              { Bt = Wv; C = Vo; n0 = (long long)(nt - 20) * 128; N = KVD; }
    const long long m0 = (long long)blockIdx.y * 128;
    const int t = threadIdx.x, w = t >> 5, lane = t & 31, g = lane >> 2, tg = lane & 3;
    const int wm = w >> 2, wn = w & 3;
    float acc[4][4][4] = {};
    gemm_core(X, Bt, m0, n0, DMODEL, gsm, t, acc);
    #pragma unroll
    for (int fm = 0; fm < 4; fm++) {
        const long long r0 = m0 + wm * 64 + fm * 16 + g;
        #pragma unroll
        for (int fn = 0; fn < 4; fn++) {
            const long long cc = n0 + wn * 32 + fn * 8 + 2 * tg;
            *(uint32_t*)(C + r0 * N + cc)       = f2h2(acc[fm][fn][0], acc[fm][fn][1]);
            *(uint32_t*)(C + (r0 + 8) * N + cc) = f2h2(acc[fm][fn][2], acc[fm][fn][3]);
        }
    }
}

__global__ __launch_bounds__(256) void out_gemm(const __half* __restrict__ A,
                                                const __half* __restrict__ Bt,
                                                float* __restrict__ C) {
    extern __shared__ __half gsm[];
    const long long m0 = (long long)blockIdx.y * 128, n0 = (long long)blockIdx.x * 128;
    const int t = threadIdx.x, w = t >> 5, lane = t & 31, g = lane >> 2, tg = lane & 3;
    const int wm = w >> 2, wn = w & 3;
    float acc[4][4][4] = {};
    gemm_core(A, Bt, m0, n0, DMODEL, gsm, t, acc);
    #pragma unroll
    for (int fm = 0; fm < 4; fm++) {
        const long long r0 = m0 + wm * 64 + fm * 16 + g;
        #pragma unroll
        for (int fn = 0; fn < 4; fn++) {
            const long long cc = n0 + wn * 32 + fn * 8 + 2 * tg;
            *(float2*)(C + r0 * DMODEL + cc)       = make_float2(acc[fm][fn][0], acc[fm][fn][1]);
            *(float2*)(C + (r0 + 8) * DMODEL + cc) = make_float2(acc[fm][fn][2], acc[fm][fn][3]);
        }
    }
}

// -------- fused attention: clean/boundary split + exp2 softmax + dbuf KV + trans-V --------
#define A_KV 9216
#define KVBUF 18432
#define ATT_SMB ((9216 + 2 * KVBUF) * 2)   // 92160 B

__global__ __launch_bounds__(256) void attn_fused(const __half* __restrict__ Q,
                                                  const __half* __restrict__ Kg,
                                                  const __half* __restrict__ Vg,
                                                  __half* __restrict__ O) {
    extern __shared__ __half smh[];
    __half* QS = smh;

    const int bh = blockIdx.y, b = bh >> 5, h = bh & 31, kh = h >> 2;
    const int i0 = blockIdx.x * 128;
    const int t = threadIdx.x, w = t >> 5, lane = t & 31, g = lane >> 2, tg = lane & 3;
    const int lr = t >> 1, half = t & 1;
    const uint32_t smb = (uint32_t)__cvta_generic_to_shared(smh);
    const uint32_t k_rel = ((((lane >> 4) << 3) + (lane & 7)) * QKP + ((lane >> 3) & 1) * 8) * 2;
    const uint32_t v_rel = ((lane & 15) * QKP + (lane >> 4) * 8) * 2;

    {   // stage Q tile (128 x 64 halves)
        const __half* qp = Q + ((long long)(b * LSEQ + i0 + lr)) * DMODEL + h * HD + half * 32;
        #pragma unroll
        for (int f = 0; f < 4; f++)
            *(uint4*)&QS[lr * QKP + half * 32 + f * 8] = *(const uint4*)(qp + f * 8);
    }
    const __half* kbase = Kg + ((long long)(b * LSEQ + lr)) * KVD + kh * HD + half * 32;
    const __half* vbase = Vg + ((long long)(b * LSEQ + lr)) * KVD + kh * HD + half * 32;

    int aj[16], na = 0;
    #pragma unroll
    for (int jt = 0; jt < 16; jt++) {
        const int j0 = jt << 7;
        if (!tile_dead(i0, j0)) aj[na++] = j0;
    }

    uint4 kpre[4], vpre[4];
    {
        const __half* kp = kbase + (long long)aj[0] * KVD;
        const __half* vp = vbase + (long long)aj[0] * KVD;
        #pragma unroll
        for (int f = 0; f < 4; f++) { kpre[f] = *(const uint4*)(kp + f * 8); vpre[f] = *(const uint4*)(vp + f * 8); }
        __half* KS0 = smh + A_KV;
        __half* VS0 = KS0 + 9216;
        #pragma unroll
        for (int f = 0; f < 4; f++) {
            *(uint4*)&KS0[lr * QKP + half * 32 + f * 8] = kpre[f];
            *(uint4*)&VS0[lr * QKP + half * 32 + f * 8] = vpre[f];
        }
    }
    __syncthreads();

    uint32_t qf[4][4];
    const int rw = w * 16 + g;
    {
        const uint32_t q_lane = smb + (((w * 16 + (lane & 15)) * QKP) + (lane >> 4) * 8) * 2;
        #pragma unroll
        for (int kk = 0; kk < 4; kk++)
            ldsm4(qf[kk], q_lane + kk * 16 * 2);
    }

    const int gi0 = i0 + rw, gi1 = gi0 + 8;
    float l0 = 0.0f, l1 = 0.0f;
    float oacc[8][4] = {};

    for (int ci = 0; ci < na; ci++) {
        const int j0 = aj[ci];
        const uint32_t kvo = (uint32_t)(ci & 1) * KVBUF * 2;
        const uint32_t k_lane = smb + (A_KV * 2) + kvo + k_rel;
        const uint32_t v_lane = smb + ((A_KV + 9216) * 2) + kvo + v_rel;

        if (ci + 1 < na) {
            const int jn = aj[ci + 1];
            const __half* kp = kbase + (long long)jn * KVD;
            const __half* vp = vbase + (long long)jn * KVD;
            #pragma unroll
            for (int f = 0; f < 4; f++) { kpre[f] = *(const uint4*)(kp + f * 8); vpre[f] = *(const uint4*)(vp + f * 8); }
        }

        float sacc[16][4] = {};
        #pragma unroll
        for (int kk = 0; kk < 4; kk++) {
            const uint32_t koff = kk * 16 * 2;
            #pragma unroll
            for (int p = 0; p < 8; p++) {
                uint32_t bf[4];
                ldsm4(bf, k_lane + p * (16 * QKP * 2) + koff);
                mma16(sacc[2 * p],     qf[kk], bf);
                mma16(sacc[2 * p + 1], qf[kk], bf + 2);
            }
        }

        if (ci + 1 < na) {
            __half* KSn = smh + A_KV + ((ci + 1) & 1) * KVBUF;
            __half* VSn = KSn + 9216;
            #pragma unroll
            for (int f = 0; f < 4; f++) {
                *(uint4*)&KSn[lr * QKP + half * 32 + f * 8] = kpre[f];
                *(uint4*)&VSn[lr * QKP + half * 32 + f * 8] = vpre[f];
            }
        }

        // ---- fixed-base softmax (exp2); clean tiles skip mask predicates ----
        const bool clean = (j0 >= i0 + 128) || (j0 + 127 < i0 - WWIN);
        uint32_t ph0[16], ph1[16];
        float rs0 = 0.0f, rs1 = 0.0f;
        if (clean) {
            #pragma unroll
            for (int fn = 0; fn < 16; fn++) {
                const float p00 = exp2f(sacc[fn][0] * EXSC), p01 = exp2f(sacc[fn][1] * EXSC);
                const float p10 = exp2f(sacc[fn][2] * EXSC), p11 = exp2f(sacc[fn][3] * EXSC);
                rs0 += p00 + p01; rs1 += p10 + p11;
                ph0[fn] = f2h2(p00, p01);
                ph1[fn] = f2h2(p10, p11);
            }
        } else {
            #pragma unroll
            for (int fn = 0; fn < 16; fn++) {
                float p0[2], p1[2];
                #pragma unroll
                for (int e = 0; e < 2; e++) {
                    const int gj = j0 + fn * 8 + 2 * tg + e;
                    const bool m0 = (gj >= gi0 - WWIN) && (gj < gi0);
                    const bool m1 = (gj >= gi1 - WWIN) && (gj < gi1);
                    p0[e] = m0 ? 0.0f : exp2f(sacc[fn][e] * EXSC);
                    p1[e] = m1 ? 0.0f : exp2f(sacc[fn][2 + e] * EXSC);
                }
                rs0 += p0[0] + p0[1]; rs1 += p1[0] + p1[1];
                ph0[fn] = f2h2(p0[0], p0[1]);
                ph1[fn] = f2h2(p1[0], p1[1]);
            }
        }
        rs0 += __shfl_xor_sync(0xffffffffu, rs0, 1);
        rs0 += __shfl_xor_sync(0xffffffffu, rs0, 2);
        rs1 += __shfl_xor_sync(0xffffffffu, rs1, 1);
        rs1 += __shfl_xor_sync(0xffffffffu, rs1, 2);
        l0 += rs0; l1 += rs1;

        #pragma unroll
        for (int kk = 0; kk < 8; kk++) {
            const uint32_t jo = kk * (16 * QKP * 2);
            uint32_t af[4] = { ph0[2 * kk], ph1[2 * kk], ph0[2 * kk + 1], ph1[2 * kk + 1] };
            #pragma unroll
            for (int p = 0; p < 4; p++) {
                uint32_t bf[4];
                ldsm4t(bf, v_lane + jo + p * 16 * 2);
                mma16(oacc[2 * p],     af, bf);
                mma16(oacc[2 * p + 1], af, bf + 2);
            }
        }
        __syncthreads();
    }

    const float inv0 = 1.0f / l0, inv1 = 1.0f / l1;
    __half* orow = O + ((long long)(b * LSEQ) + i0 + rw) * DMODEL + h * HD;
    #pragma unroll
    for (int fd = 0; fd < 8; fd++) {
        const int cc = fd * 8 + 2 * tg;
        *(uint32_t*)(orow + cc) = f2h2(oacc[fd][0] * inv0, oacc[fd][1] * inv0);
        *(uint32_t*)(orow + 8LL * DMODEL + cc) = f2h2(oacc[fd][2] * inv1, oacc[fd][3] * inv1);
    }
}

// -------- merged prep: cvt_x + 4 weight transposes in one launch --------
__device__ __forceinline__ void do_transpose(const float* __restrict__ src,
                                             __half* __restrict__ dst,
                                             int R, int C, int tile, int t) {
    __shared__ __half tb[32][33];
    const int tilesx = C / 32;
    const int c = (tile % tilesx) * 32, r = (tile / tilesx) * 32;
    const int tx = t & 31, ty = t >> 5;
    #pragma unroll
    for (int i = 0; i < 32; i += 8) tb[ty + i][tx] = __float2half_rn(src[(long long)(r + ty + i) * C + c + tx]);
    __syncthreads();
    #pragma unroll
    for (int i = 0; i < 32; i += 8) dst[(long long)(c + ty + i) * R + r + tx] = tb[tx][ty + i];
}
__global__ void prep_kernel(const float* __restrict__ x,
                            const float* __restrict__ wq,
                            const float* __restrict__ wk,
                            const float* __restrict__ wv,
                            const float* __restrict__ wo,
                            __half* __restrict__ xt,
                            __half* __restrict__ wqt,
                            __half* __restrict__ wkt,
                            __half* __restrict__ wvt,
                            __half* __restrict__ wot) {
    const int blk = blockIdx.x, t = threadIdx.x;
    if (blk < 4096) {
        const long long i = ((long long)blk * 256 + t) * 8;
        float4 v0 = *(const float4*)(x + i);
        float4 v1 = *(const float4*)(x + i + 4);
        uint4 u;
        u.x = f2h2(v0.x, v0.y); u.y = f2h2(v0.z, v0.w);
        u.z = f2h2(v1.x, v1.y); u.w = f2h2(v1.z, v1.w);
        *(uint4*)(xt + i) = u;
    } else if (blk < 8192) {
        do_transpose(wq, wqt, DMODEL, DMODEL, blk - 4096, t);
    } else if (blk < 9216) {
        do_transpose(wk, wkt, DMODEL, KVD, blk - 8192, t);
    } else if (blk < 10240) {
        do_transpose(wv, wvt, DMODEL, KVD, blk - 9216, t);
    } else {
        do_transpose(wo, wot, DMODEL, DMODEL, blk - 10240, t);
    }
}

// ---------------- launch ----------------
extern "C" void kernel_launch(void* const* d_in, const int* in_sizes, int n_in,
                              void* d_out, int out_size) {
    const float* x  = (const float*)d_in[0];
    const float* wq = (const float*)d_in[1];
    const float* wk = (const float*)d_in[2];
    const float* wv = (const float*)d_in[3];
    const float* wo = (const float*)d_in[4];
    float* out = (float*)d_out;

    __half *xt, *qb, *kb, *vb, *ab, *wqt, *wkt, *wvt, *wot;
    cudaGetSymbolAddress((void**)&xt, g_xt);
    cudaGetSymbolAddress((void**)&qb, g_q);
    cudaGetSymbolAddress((void**)&kb, g_k);
    cudaGetSymbolAddress((void**)&vb, g_v);
    cudaGetSymbolAddress((void**)&ab, g_ao);
    cudaGetSymbolAddress((void**)&wqt, g_wqt);
    cudaGetSymbolAddress((void**)&wkt, g_wkt);
    cudaGetSymbolAddress((void**)&wvt, g_wvt);
    cudaGetSymbolAddress((void**)&wot, g_wot);

    const int GEMM_SM = 2 * GBUFH * 2;      // 73728 B
    cudaFuncSetAttribute(qkv_gemm,   cudaFuncAttributeMaxDynamicSharedMemorySize, GEMM_SM);
    cudaFuncSetAttribute(out_gemm,   cudaFuncAttributeMaxDynamicSharedMemorySize, GEMM_SM);
    cudaFuncSetAttribute(attn_fused, cudaFuncAttributeMaxDynamicSharedMemorySize, ATT_SMB);

    prep_kernel<<<dim3(14336), 256>>>(x, wq, wk, wv, wo, xt, wqt, wkt, wvt, wot);

    qkv_gemm<<<dim3(24, 32), 256, GEMM_SM>>>(xt, wqt, wkt, wvt, qb, kb, vb);

    attn_fused<<<dim3(16, 64), 256, ATT_SMB>>>(qb, kb, vb, ab);

    out_gemm<<<dim3(16, 32), 256, GEMM_SM>>>(ab, wot, out);
}